// round 11
// baseline (speedup 1.0000x reference)
#include <cuda_runtime.h>
#include <cuda_bf16.h>
#include <cstddef>

#define B_ 32
#define T_ 512
#define H_ 1024
#define G_ 4096
#define NB 128

__device__ float g_gx[(size_t)B_ * T_ * G_];
__device__ float g_out0[(size_t)B_ * T_ * H_];
__device__ __nv_bfloat16 g_hb[2][2][(size_t)B_ * H_];   // [buf][hi/lo][b*1024+k]
__device__ unsigned g_bars[8 * 32];                      // 8 counters, 128B apart
__device__ __nv_bfloat16 g_Ahi[(size_t)B_ * T_ * H_];
__device__ __nv_bfloat16 g_Alo[(size_t)B_ * T_ * H_];
__device__ __nv_bfloat16 g_Whi[(size_t)G_ * H_];
__device__ __nv_bfloat16 g_Wlo[(size_t)G_ * H_];

// ---------------- hi/lo bf16 split conversion ---------------------------------
__global__ __launch_bounds__(256) void conv_split(
    const float* __restrict__ s, __nv_bfloat16* __restrict__ hi,
    __nv_bfloat16* __restrict__ lo, int n4)
{
    int i = blockIdx.x * 256 + threadIdx.x;
    if (i >= n4) return;
    float4 v = ((const float4*)s)[i];
    __nv_bfloat16 h0 = __float2bfloat16(v.x), h1 = __float2bfloat16(v.y);
    __nv_bfloat16 h2 = __float2bfloat16(v.z), h3 = __float2bfloat16(v.w);
    __nv_bfloat16 l0 = __float2bfloat16(v.x - __bfloat162float(h0));
    __nv_bfloat16 l1 = __float2bfloat16(v.y - __bfloat162float(h1));
    __nv_bfloat16 l2 = __float2bfloat16(v.z - __bfloat162float(h2));
    __nv_bfloat16 l3 = __float2bfloat16(v.w - __bfloat162float(h3));
    ((__nv_bfloat162*)hi)[i * 2]     = __nv_bfloat162(h0, h1);
    ((__nv_bfloat162*)hi)[i * 2 + 1] = __nv_bfloat162(h2, h3);
    ((__nv_bfloat162*)lo)[i * 2]     = __nv_bfloat162(l0, l1);
    ((__nv_bfloat162*)lo)[i * 2 + 1] = __nv_bfloat162(l2, l3);
}

// ---------------- mma helpers --------------------------------------------------
__device__ __forceinline__ void ldsm4(unsigned* r, unsigned a) {
    asm volatile("ldmatrix.sync.aligned.m8n8.x4.shared.b16 {%0,%1,%2,%3}, [%4];"
                 : "=r"(r[0]), "=r"(r[1]), "=r"(r[2]), "=r"(r[3]) : "r"(a));
}
__device__ __forceinline__ void mma16816(float* c, const unsigned* a,
                                         unsigned b0, unsigned b1) {
    asm volatile(
        "mma.sync.aligned.m16n8k16.row.col.f32.bf16.bf16.f32 "
        "{%0,%1,%2,%3}, {%4,%5,%6,%7}, {%8,%9}, {%0,%1,%2,%3};"
        : "+f"(c[0]), "+f"(c[1]), "+f"(c[2]), "+f"(c[3])
        : "r"(a[0]), "r"(a[1]), "r"(a[2]), "r"(a[3]), "r"(b0), "r"(b1));
}
__device__ __forceinline__ void cpa(unsigned s, const void* g) {
    asm volatile("cp.async.cg.shared.global [%0], [%1], 16;" :: "r"(s), "l"(g));
}

// ---------------- tensor-core GEMM (unchanged) --------------------------------
#define SR 40
#define BUFB (128 * SR * 2)
#define OFF_AH 0
#define OFF_AL (2 * BUFB)
#define OFF_BH (4 * BUFB)
#define OFF_BL (6 * BUFB)
#define TC_SMEM (8 * BUFB)

__global__ __launch_bounds__(256, 1) void tc_gemm(
    const __nv_bfloat16* __restrict__ Ahi, const __nv_bfloat16* __restrict__ Alo,
    const __nv_bfloat16* __restrict__ Whi, const __nv_bfloat16* __restrict__ Wlo,
    const float* __restrict__ bias)
{
    extern __shared__ char sm[];
    const unsigned sbase = (unsigned)__cvta_generic_to_shared(sm);
    const int tid = threadIdx.x, lane = tid & 31, wid = tid >> 5;
    const int wm = wid & 3, wn = wid >> 2;
    const int m0 = blockIdx.y * 128, n0 = blockIdx.x * 128;

    int frow[2], fch[2];
    unsigned sA[2];
#pragma unroll
    for (int u = 0; u < 2; ++u) {
        int id = tid + 256 * u;
        frow[u] = id >> 2; fch[u] = (id & 3) * 8;
        sA[u] = (frow[u] * SR + fch[u]) * 2;
    }
    const int arow = wm * 32 + (lane & 7) + (lane & 8);
    const unsigned a_base = (arow * SR + (lane >> 4) * 8) * 2;
    const int brow = wn * 64 + (lane & 7) + (lane >> 4) * 8;
    const unsigned b_base = (brow * SR + ((lane >> 3) & 1) * 8) * 2;

    float c[2][8][4];
#pragma unroll
    for (int i = 0; i < 2; ++i)
#pragma unroll
        for (int j = 0; j < 8; ++j)
#pragma unroll
            for (int q = 0; q < 4; ++q) c[i][j][q] = 0.f;

#pragma unroll
    for (int u = 0; u < 2; ++u) {
        size_t ga = (size_t)(m0 + frow[u]) * H_ + fch[u];
        size_t gb = (size_t)(n0 + frow[u]) * H_ + fch[u];
        cpa(sbase + OFF_AH + sA[u], &Ahi[ga]);
        cpa(sbase + OFF_AL + sA[u], &Alo[ga]);
        cpa(sbase + OFF_BH + sA[u], &Whi[gb]);
        cpa(sbase + OFF_BL + sA[u], &Wlo[gb]);
    }
    asm volatile("cp.async.commit_group;");

    for (int s = 0; s < 32; ++s) {
        asm volatile("cp.async.wait_group 0;");
        __syncthreads();
        if (s + 1 < 32) {
            int k0 = (s + 1) * 32, bf = (s + 1) & 1;
#pragma unroll
            for (int u = 0; u < 2; ++u) {
                size_t ga = (size_t)(m0 + frow[u]) * H_ + k0 + fch[u];
                size_t gb = (size_t)(n0 + frow[u]) * H_ + k0 + fch[u];
                cpa(sbase + OFF_AH + bf * BUFB + sA[u], &Ahi[ga]);
                cpa(sbase + OFF_AL + bf * BUFB + sA[u], &Alo[ga]);
                cpa(sbase + OFF_BH + bf * BUFB + sA[u], &Whi[gb]);
                cpa(sbase + OFF_BL + bf * BUFB + sA[u], &Wlo[gb]);
            }
            asm volatile("cp.async.commit_group;");
        }
        const unsigned bo = (s & 1) * BUFB;
#pragma unroll
        for (int kk = 0; kk < 2; ++kk) {
            unsigned ah[2][4], al[2][4], bh[4][4], bl[4][4];
#pragma unroll
            for (int mi = 0; mi < 2; ++mi) {
                unsigned ad = sbase + bo + a_base + mi * (16 * SR * 2) + kk * 32;
                ldsm4(ah[mi], ad + OFF_AH);
                ldsm4(al[mi], ad + OFF_AL);
            }
#pragma unroll
            for (int j = 0; j < 4; ++j) {
                unsigned bd = sbase + bo + b_base + j * (16 * SR * 2) + kk * 32;
                ldsm4(bh[j], bd + OFF_BH);
                ldsm4(bl[j], bd + OFF_BL);
            }
#pragma unroll
            for (int mi = 0; mi < 2; ++mi)
#pragma unroll
                for (int j = 0; j < 4; ++j) {
                    mma16816(c[mi][2*j],   ah[mi], bh[j][0], bh[j][1]);
                    mma16816(c[mi][2*j+1], ah[mi], bh[j][2], bh[j][3]);
                    mma16816(c[mi][2*j],   ah[mi], bl[j][0], bl[j][1]);
                    mma16816(c[mi][2*j+1], ah[mi], bl[j][2], bl[j][3]);
                    mma16816(c[mi][2*j],   al[mi], bh[j][0], bh[j][1]);
                    mma16816(c[mi][2*j+1], al[mi], bh[j][2], bh[j][3]);
                }
        }
        __syncthreads();
    }
#pragma unroll
    for (int mi = 0; mi < 2; ++mi) {
        int gr = m0 + wm * 32 + mi * 16 + (lane >> 2);
#pragma unroll
        for (int ni = 0; ni < 8; ++ni) {
            int gc = n0 + wn * 64 + ni * 8 + (lane & 3) * 2;
            float2 bv = *(const float2*)&bias[gc];
            float* cc = c[mi][ni];
            *(float2*)&g_gx[(size_t)gr * G_ + gc] =
                make_float2(cc[0] + bv.x, cc[1] + bv.y);
            *(float2*)&g_gx[(size_t)(gr + 8) * G_ + gc] =
                make_float2(cc[2] + bv.x, cc[3] + bv.y);
        }
    }
}

// ---------------- persistent tensorized LSTM recurrence (warp-autonomous) -----
__device__ __forceinline__ float sigf(float x) { return 1.0f / (1.0f + __expf(-x)); }

__device__ __forceinline__ void grid_bar(int bid, unsigned wantc) {
    __syncthreads();
    if (threadIdx.x < 8) {
        if (threadIdx.x == 0)
            asm volatile("red.release.gpu.global.add.u32 [%0], 1;"
                         :: "l"(&g_bars[(bid & 7) * 32]) : "memory");
        unsigned v;
        do {
            asm volatile("ld.acquire.gpu.global.u32 %0, [%1];"
                         : "=r"(v) : "l"(&g_bars[threadIdx.x * 32]));
        } while (v < wantc);
    }
    __syncthreads();
}

// SMEM map (bytes):
//  [0, 66048)            Wlo  [32 rows][1032 elems] bf16 (persistent)
//  [66048, 205312)       8 warp regions x 17408B:
//                          init: Whi temp (WSTR layout, first 66048B)
//                          per step: h slice [plane2][32 b][136 elems] stride 272B
//                          post-mma: partials overlay [32 m][36 n] f32 (4608B)
//  [205312, 209920)      g_s [32][36] f32
//  [209920, 210048)      len
#define WSTR 1032
#define OFF_WLO 0
#define OFF_H   66048
#define WREG    17408
#define HPL     8704                // plane size within warp region
#define OFF_GS  205312
#define OFF_LEN 209920
#define REC_SMEM 210048

__global__ __launch_bounds__(256, 1) void lstm_rec(
    const float* __restrict__ whh, const void* __restrict__ len_raw,
    float* __restrict__ outp, float* __restrict__ cdst, float* __restrict__ hdst)
{
    extern __shared__ char sm[];
    const unsigned sbase = (unsigned)__cvta_generic_to_shared(sm);
    float* g_s = (float*)(sm + OFF_GS);
    int* len_s = (int*)(sm + OFF_LEN);

    const int tid = threadIdx.x, lane = tid & 31, kw = tid >> 5;
    const int bid = blockIdx.x;
    const int j0 = bid * 8;

    if (tid == 0) {
        const int* L = (const int*)len_raw;
        bool is64 = true;
        for (int i = 1; i < 32; i += 2) if (L[i] != 0) { is64 = false; break; }
        for (int b = 0; b < 32; ++b) len_s[b] = is64 ? L[2 * b] : L[b];
    }

    // ---- stage + split W_hh slice: Whi -> temp (OFF_H), Wlo -> OFF_WLO --------
    {
        const int r = tid & 31;
        const int grow = (r >> 3) * 1024 + j0 + (r & 7);
        const int k0 = (tid >> 5) * 128;
        const float* src = &whh[(size_t)grow * H_ + k0];
        __nv_bfloat162* whi = (__nv_bfloat162*)(sm + OFF_H);
        __nv_bfloat162* wlo = (__nv_bfloat162*)(sm + OFF_WLO);
#pragma unroll
        for (int kk = 0; kk < 128; kk += 4) {
            float4 v = *(const float4*)&src[kk];
            __nv_bfloat16 h0 = __float2bfloat16(v.x), h1 = __float2bfloat16(v.y);
            __nv_bfloat16 h2 = __float2bfloat16(v.z), h3 = __float2bfloat16(v.w);
            int e = r * WSTR + k0 + kk;
            whi[e / 2]     = __nv_bfloat162(h0, h1);
            whi[e / 2 + 1] = __nv_bfloat162(h2, h3);
            wlo[e / 2]     = __nv_bfloat162(__float2bfloat16(v.x - __bfloat162float(h0)),
                                            __float2bfloat16(v.y - __bfloat162float(h1)));
            wlo[e / 2 + 1] = __nv_bfloat162(__float2bfloat16(v.z - __bfloat162float(h2)),
                                            __float2bfloat16(v.w - __bfloat162float(h3)));
        }
    }
    __syncthreads();

    // ---- A-operand addressing + persistent Whi register fragments ------------
    const unsigned a_off = ((lane & 7) + (lane & 8)) * (WSTR * 2) + ((lane >> 4) * 8) * 2;
    unsigned wa[8][2][4];
#pragma unroll
    for (int kt = 0; kt < 8; ++kt)
#pragma unroll
        for (int mi = 0; mi < 2; ++mi)
            ldsm4(wa[kt][mi],
                  sbase + OFF_H + a_off + ((mi * 16) * WSTR + kw * 128 + kt * 16) * 2);
    __syncthreads();          // temp Whi region free for h staging

    const unsigned alo0 = sbase + OFF_WLO + a_off + (kw * 128) * 2;          // mi=0
    const unsigned alo1 = alo0 + (16 * WSTR) * 2;                             // mi=1

    // ---- B-operand (h) addressing: warp-private region, stride 272B ----------
    const unsigned hreg = sbase + OFF_H + kw * WREG;
    const unsigned bb0 = hreg + ((0 * 16 + (lane & 7) + ((lane >> 4) & 1) * 8) * 272)
                              + ((lane >> 3) & 1) * 16;   // batches 0-15
    const unsigned bb1 = hreg + ((1 * 16 + (lane & 7) + ((lane >> 4) & 1) * 8) * 272)
                              + ((lane >> 3) & 1) * 16;   // batches 16-31

    // reduce / gx map
    const int rm = tid >> 3, rb = (tid & 7) * 4;
    const size_t ocol = (size_t)(rm >> 3) * 1024 + j0 + (rm & 7);

    // update map
    const int ju = tid & 7, bu = tid >> 3;
    float c_reg = 0.f, h_reg = 0.f;
    g_hb[0][0][bu * H_ + j0 + ju] = __float2bfloat16(0.f);
    g_hb[0][1][bu * H_ + j0 + ju] = __float2bfloat16(0.f);

    unsigned wantc = 16;
    grid_bar(bid, wantc);

    for (int t = 0; t < T_; ++t) {
        // gx prefetch for reduce phase
        float gxv[4];
#pragma unroll
        for (int e = 0; e < 4; ++e)
            gxv[e] = __ldg(&g_gx[((size_t)(rb + e) * T_ + t) * G_ + ocol]);

        // ---- warp-private staging: lane = batch row, 16 uint4 per plane ------
#pragma unroll
        for (int pl = 0; pl < 2; ++pl) {
            const uint4* src = (const uint4*)(g_hb[t & 1][pl] + (size_t)lane * H_ + kw * 128);
            char* dst = sm + OFF_H + kw * WREG + pl * HPL + lane * 272;
            uint4 v[8];
#pragma unroll
            for (int u = 0; u < 8; ++u) v[u] = __ldcg(src + u);
#pragma unroll
            for (int u = 0; u < 8; ++u) *(uint4*)(dst + u * 16) = v[u];
#pragma unroll
            for (int u = 0; u < 8; ++u) v[u] = __ldcg(src + 8 + u);
#pragma unroll
            for (int u = 0; u < 8; ++u) *(uint4*)(dst + 128 + u * 16) = v[u];
        }
        __syncwarp();

        // ---- mma: 8 k-tiles, W-hi from registers ----------------------------
        float c[2][4][4];
#pragma unroll
        for (int mi = 0; mi < 2; ++mi)
#pragma unroll
            for (int nt = 0; nt < 4; ++nt)
#pragma unroll
                for (int q = 0; q < 4; ++q) c[mi][nt][q] = 0.f;

#pragma unroll
        for (int kt = 0; kt < 8; ++kt) {
            unsigned bh0[4], bh1[4], bl0[4], bl1[4], al0[4], al1[4];
            ldsm4(bh0, bb0 + kt * 32);
            ldsm4(bh1, bb1 + kt * 32);
            ldsm4(bl0, bb0 + HPL + kt * 32);
            ldsm4(bl1, bb1 + HPL + kt * 32);
            ldsm4(al0, alo0 + kt * 32);
            ldsm4(al1, alo1 + kt * 32);
            // hi*hi
            mma16816(c[0][0], wa[kt][0], bh0[0], bh0[1]);
            mma16816(c[0][1], wa[kt][0], bh0[2], bh0[3]);
            mma16816(c[0][2], wa[kt][0], bh1[0], bh1[1]);
            mma16816(c[0][3], wa[kt][0], bh1[2], bh1[3]);
            mma16816(c[1][0], wa[kt][1], bh0[0], bh0[1]);
            mma16816(c[1][1], wa[kt][1], bh0[2], bh0[3]);
            mma16816(c[1][2], wa[kt][1], bh1[0], bh1[1]);
            mma16816(c[1][3], wa[kt][1], bh1[2], bh1[3]);
            // hi*lo
            mma16816(c[0][0], wa[kt][0], bl0[0], bl0[1]);
            mma16816(c[0][1], wa[kt][0], bl0[2], bl0[3]);
            mma16816(c[0][2], wa[kt][0], bl1[0], bl1[1]);
            mma16816(c[0][3], wa[kt][0], bl1[2], bl1[3]);
            mma16816(c[1][0], wa[kt][1], bl0[0], bl0[1]);
            mma16816(c[1][1], wa[kt][1], bl0[2], bl0[3]);
            mma16816(c[1][2], wa[kt][1], bl1[0], bl1[1]);
            mma16816(c[1][3], wa[kt][1], bl1[2], bl1[3]);
            // lo*hi
            mma16816(c[0][0], al0, bh0[0], bh0[1]);
            mma16816(c[0][1], al0, bh0[2], bh0[3]);
            mma16816(c[0][2], al0, bh1[0], bh1[1]);
            mma16816(c[0][3], al0, bh1[2], bh1[3]);
            mma16816(c[1][0], al1, bh0[0], bh0[1]);
            mma16816(c[1][1], al1, bh0[2], bh0[3]);
            mma16816(c[1][2], al1, bh1[0], bh1[1]);
            mma16816(c[1][3], al1, bh1[2], bh1[3]);
        }

        // ---- partials overlay own region: [32 m][36 n] f32 -------------------
        {
            float* red = (float*)(sm + OFF_H + kw * WREG);
#pragma unroll
            for (int mi = 0; mi < 2; ++mi)
#pragma unroll
                for (int nt = 0; nt < 4; ++nt) {
                    int m = mi * 16 + (lane >> 2);
                    int n = nt * 8 + (lane & 3) * 2;
                    *(float2*)&red[m * 36 + n]       = make_float2(c[mi][nt][0], c[mi][nt][1]);
                    *(float2*)&red[(m + 8) * 36 + n] = make_float2(c[mi][nt][2], c[mi][nt][3]);
                }
        }
        __syncthreads();

        // ---- reduce over 8 warp partials + gx --------------------------------
        {
            float s0 = gxv[0], s1 = gxv[1], s2 = gxv[2], s3 = gxv[3];
#pragma unroll
            for (int s = 0; s < 8; ++s) {
                float4 p = *(float4*)((float*)(sm + OFF_H + s * WREG) + rm * 36 + rb);
                s0 += p.x; s1 += p.y; s2 += p.z; s3 += p.w;
            }
            *(float4*)&g_s[rm * 36 + rb] = make_float4(s0, s1, s2, s3);
        }
        __syncthreads();

        // ---- pointwise update (fp32 state) -----------------------------------
        {
            float fg = sigf(g_s[(0 * 8 + ju) * 36 + bu]);
            float ig = sigf(g_s[(1 * 8 + ju) * 36 + bu]);
            float og = sigf(g_s[(2 * 8 + ju) * 36 + bu]);
            float cg = tanhf(g_s[(3 * 8 + ju) * 36 + bu]);
            float cn = fg * c_reg + ig * cg;
            float hn = og * tanhf(cn);
            if (t < len_s[bu]) { c_reg = cn; h_reg = hn; }
            __nv_bfloat16 hh = __float2bfloat16(h_reg);
            __nv_bfloat16 hl = __float2bfloat16(h_reg - __bfloat162float(hh));
            int nbuf = (t & 1) ^ 1;
            g_hb[nbuf][0][bu * H_ + j0 + ju] = hh;
            g_hb[nbuf][1][bu * H_ + j0 + ju] = hl;
            outp[((size_t)bu * T_ + t) * H_ + (j0 + ju)] = h_reg;
        }

        wantc += 16;
        grid_bar(bid, wantc);
    }
    cdst[(size_t)bu * H_ + j0 + ju] = c_reg;
    hdst[(size_t)bu * H_ + j0 + ju] = h_reg;
}

extern "C" void kernel_launch(void* const* d_in, const int* in_sizes, int n_in,
                              void* d_out, int out_size)
{
    const float* x    = (const float*)d_in[0];
    const void*  len  = d_in[1];
    const float* wih0 = (const float*)d_in[2];
    const float* whh0 = (const float*)d_in[3];
    const float* b0   = (const float*)d_in[4];
    const float* wih1 = (const float*)d_in[5];
    const float* whh1 = (const float*)d_in[6];
    const float* b1   = (const float*)d_in[7];
    float* out = (float*)d_out;

    void *bar_p, *out0_p, *ahi_p, *alo_p, *whi_p, *wlo_p;
    cudaGetSymbolAddress(&bar_p, g_bars);
    cudaGetSymbolAddress(&out0_p, g_out0);
    cudaGetSymbolAddress(&ahi_p, g_Ahi);
    cudaGetSymbolAddress(&alo_p, g_Alo);
    cudaGetSymbolAddress(&whi_p, g_Whi);
    cudaGetSymbolAddress(&wlo_p, g_Wlo);
    float* out0 = (float*)out0_p;
    __nv_bfloat16* Ahi = (__nv_bfloat16*)ahi_p;
    __nv_bfloat16* Alo = (__nv_bfloat16*)alo_p;
    __nv_bfloat16* Whi = (__nv_bfloat16*)whi_p;
    __nv_bfloat16* Wlo = (__nv_bfloat16*)wlo_p;

    cudaFuncSetAttribute(lstm_rec, cudaFuncAttributeMaxDynamicSharedMemorySize, REC_SMEM);
    cudaFuncSetAttribute(tc_gemm, cudaFuncAttributeMaxDynamicSharedMemorySize, TC_SMEM);

    const size_t O1 = (size_t)B_ * T_ * H_;
    float* c0dst = out + O1;
    float* c1dst = out + O1 + (size_t)B_ * H_;
    float* h0dst = out + O1 + 2 * (size_t)B_ * H_;
    float* h1dst = out + O1 + 3 * (size_t)B_ * H_;

    const int nA4 = (B_ * T_ * H_) / 4;
    const int nW4 = (G_ * H_) / 4;
    dim3 gg(G_ / 128, (B_ * T_) / 128);

    conv_split<<<nW4 / 256, 256>>>(wih0, Whi, Wlo, nW4);
    conv_split<<<nA4 / 256, 256>>>(x, Ahi, Alo, nA4);
    tc_gemm<<<gg, 256, TC_SMEM>>>(Ahi, Alo, Whi, Wlo, b0);
    cudaMemsetAsync(bar_p, 0, 8 * 32 * sizeof(unsigned), 0);
    lstm_rec<<<NB, 256, REC_SMEM>>>(whh0, len, out0, c0dst, h0dst);

    conv_split<<<nW4 / 256, 256>>>(wih1, Whi, Wlo, nW4);
    conv_split<<<nA4 / 256, 256>>>(out0, Ahi, Alo, nA4);
    tc_gemm<<<gg, 256, TC_SMEM>>>(Ahi, Alo, Whi, Wlo, b1);
    cudaMemsetAsync(bar_p, 0, 8 * 32 * sizeof(unsigned), 0);
    lstm_rec<<<NB, 256, REC_SMEM>>>(whh1, len, out, c1dst, h1dst);
}

// round 13
// speedup vs baseline: 1.2740x; 1.2740x over previous
#include <cuda_runtime.h>
#include <cuda_bf16.h>
#include <cstddef>

#define B_ 32
#define T_ 512
#define H_ 1024
#define G_ 4096
#define NB 128

__device__ float g_gx[(size_t)B_ * T_ * G_];
__device__ float g_out0[(size_t)B_ * T_ * H_];
__device__ __nv_bfloat16 g_hb[2][2][(size_t)B_ * H_];
__device__ unsigned g_bars[8 * 32];
__device__ __nv_bfloat16 g_Ahi[(size_t)B_ * T_ * H_];
__device__ __nv_bfloat16 g_Alo[(size_t)B_ * T_ * H_];
__device__ __nv_bfloat16 g_Whi[(size_t)G_ * H_];
__device__ __nv_bfloat16 g_Wlo[(size_t)G_ * H_];

__global__ __launch_bounds__(256) void conv_split(
    const float* __restrict__ s, __nv_bfloat16* __restrict__ hi,
    __nv_bfloat16* __restrict__ lo, int n4)
{
    int i = blockIdx.x * 256 + threadIdx.x;
    if (i >= n4) return;
    float4 v = ((const float4*)s)[i];
    __nv_bfloat16 h0 = __float2bfloat16(v.x), h1 = __float2bfloat16(v.y);
    __nv_bfloat16 h2 = __float2bfloat16(v.z), h3 = __float2bfloat16(v.w);
    __nv_bfloat16 l0 = __float2bfloat16(v.x - __bfloat162float(h0));
    __nv_bfloat16 l1 = __float2bfloat16(v.y - __bfloat162float(h1));
    __nv_bfloat16 l2 = __float2bfloat16(v.z - __bfloat162float(h2));
    __nv_bfloat16 l3 = __float2bfloat16(v.w - __bfloat162float(h3));
    ((__nv_bfloat162*)hi)[i * 2]     = __nv_bfloat162(h0, h1);
    ((__nv_bfloat162*)hi)[i * 2 + 1] = __nv_bfloat162(h2, h3);
    ((__nv_bfloat162*)lo)[i * 2]     = __nv_bfloat162(l0, l1);
    ((__nv_bfloat162*)lo)[i * 2 + 1] = __nv_bfloat162(l2, l3);
}

__device__ __forceinline__ void ldsm4(unsigned* r, unsigned a) {
    asm volatile("ldmatrix.sync.aligned.m8n8.x4.shared.b16 {%0,%1,%2,%3}, [%4];"
                 : "=r"(r[0]), "=r"(r[1]), "=r"(r[2]), "=r"(r[3]) : "r"(a));
}
__device__ __forceinline__ void mma16816(float* c, const unsigned* a,
                                         unsigned b0, unsigned b1) {
    asm volatile(
        "mma.sync.aligned.m16n8k16.row.col.f32.bf16.bf16.f32 "
        "{%0,%1,%2,%3}, {%4,%5,%6,%7}, {%8,%9}, {%0,%1,%2,%3};"
        : "+f"(c[0]), "+f"(c[1]), "+f"(c[2]), "+f"(c[3])
        : "r"(a[0]), "r"(a[1]), "r"(a[2]), "r"(a[3]), "r"(b0), "r"(b1));
}
__device__ __forceinline__ void cpa(unsigned s, const void* g) {
    asm volatile("cp.async.cg.shared.global [%0], [%1], 16;" :: "r"(s), "l"(g));
}

// ---------------- tensor-core GEMM (unchanged) --------------------------------
#define SR 40
#define BUFB (128 * SR * 2)
#define OFF_AH 0
#define OFF_AL (2 * BUFB)
#define OFF_BH (4 * BUFB)
#define OFF_BL (6 * BUFB)
#define TC_SMEM (8 * BUFB)

__global__ __launch_bounds__(256, 1) void tc_gemm(
    const __nv_bfloat16* __restrict__ Ahi, const __nv_bfloat16* __restrict__ Alo,
    const __nv_bfloat16* __restrict__ Whi, const __nv_bfloat16* __restrict__ Wlo,
    const float* __restrict__ bias)
{
    extern __shared__ char sm[];
    const unsigned sbase = (unsigned)__cvta_generic_to_shared(sm);
    const int tid = threadIdx.x, lane = tid & 31, wid = tid >> 5;
    const int wm = wid & 3, wn = wid >> 2;
    const int m0 = blockIdx.y * 128, n0 = blockIdx.x * 128;

    int frow[2], fch[2];
    unsigned sA[2];
#pragma unroll
    for (int u = 0; u < 2; ++u) {
        int id = tid + 256 * u;
        frow[u] = id >> 2; fch[u] = (id & 3) * 8;
        sA[u] = (frow[u] * SR + fch[u]) * 2;
    }
    const int arow = wm * 32 + (lane & 7) + (lane & 8);
    const unsigned a_base = (arow * SR + (lane >> 4) * 8) * 2;
    const int brow = wn * 64 + (lane & 7) + (lane >> 4) * 8;
    const unsigned b_base = (brow * SR + ((lane >> 3) & 1) * 8) * 2;

    float c[2][8][4];
#pragma unroll
    for (int i = 0; i < 2; ++i)
#pragma unroll
        for (int j = 0; j < 8; ++j)
#pragma unroll
            for (int q = 0; q < 4; ++q) c[i][j][q] = 0.f;

#pragma unroll
    for (int u = 0; u < 2; ++u) {
        size_t ga = (size_t)(m0 + frow[u]) * H_ + fch[u];
        size_t gb = (size_t)(n0 + frow[u]) * H_ + fch[u];
        cpa(sbase + OFF_AH + sA[u], &Ahi[ga]);
        cpa(sbase + OFF_AL + sA[u], &Alo[ga]);
        cpa(sbase + OFF_BH + sA[u], &Whi[gb]);
        cpa(sbase + OFF_BL + sA[u], &Wlo[gb]);
    }
    asm volatile("cp.async.commit_group;");

    for (int s = 0; s < 32; ++s) {
        asm volatile("cp.async.wait_group 0;");
        __syncthreads();
        if (s + 1 < 32) {
            int k0 = (s + 1) * 32, bf = (s + 1) & 1;
#pragma unroll
            for (int u = 0; u < 2; ++u) {
                size_t ga = (size_t)(m0 + frow[u]) * H_ + k0 + fch[u];
                size_t gb = (size_t)(n0 + frow[u]) * H_ + k0 + fch[u];
                cpa(sbase + OFF_AH + bf * BUFB + sA[u], &Ahi[ga]);
                cpa(sbase + OFF_AL + bf * BUFB + sA[u], &Alo[ga]);
                cpa(sbase + OFF_BH + bf * BUFB + sA[u], &Whi[gb]);
                cpa(sbase + OFF_BL + bf * BUFB + sA[u], &Wlo[gb]);
            }
            asm volatile("cp.async.commit_group;");
        }
        const unsigned bo = (s & 1) * BUFB;
#pragma unroll
        for (int kk = 0; kk < 2; ++kk) {
            unsigned ah[2][4], al[2][4], bh[4][4], bl[4][4];
#pragma unroll
            for (int mi = 0; mi < 2; ++mi) {
                unsigned ad = sbase + bo + a_base + mi * (16 * SR * 2) + kk * 32;
                ldsm4(ah[mi], ad + OFF_AH);
                ldsm4(al[mi], ad + OFF_AL);
            }
#pragma unroll
            for (int j = 0; j < 4; ++j) {
                unsigned bd = sbase + bo + b_base + j * (16 * SR * 2) + kk * 32;
                ldsm4(bh[j], bd + OFF_BH);
                ldsm4(bl[j], bd + OFF_BL);
            }
#pragma unroll
            for (int mi = 0; mi < 2; ++mi)
#pragma unroll
                for (int j = 0; j < 4; ++j) {
                    mma16816(c[mi][2*j],   ah[mi], bh[j][0], bh[j][1]);
                    mma16816(c[mi][2*j+1], ah[mi], bh[j][2], bh[j][3]);
                    mma16816(c[mi][2*j],   ah[mi], bl[j][0], bl[j][1]);
                    mma16816(c[mi][2*j+1], ah[mi], bl[j][2], bl[j][3]);
                    mma16816(c[mi][2*j],   al[mi], bh[j][0], bh[j][1]);
                    mma16816(c[mi][2*j+1], al[mi], bh[j][2], bh[j][3]);
                }
        }
        __syncthreads();
    }
#pragma unroll
    for (int mi = 0; mi < 2; ++mi) {
        int gr = m0 + wm * 32 + mi * 16 + (lane >> 2);
#pragma unroll
        for (int ni = 0; ni < 8; ++ni) {
            int gc = n0 + wn * 64 + ni * 8 + (lane & 3) * 2;
            float2 bv = *(const float2*)&bias[gc];
            float* cc = c[mi][ni];
            *(float2*)&g_gx[(size_t)gr * G_ + gc] =
                make_float2(cc[0] + bv.x, cc[1] + bv.y);
            *(float2*)&g_gx[(size_t)(gr + 8) * G_ + gc] =
                make_float2(cc[2] + bv.x, cc[3] + bv.y);
        }
    }
}

// ---------------- persistent tensorized LSTM recurrence (R5 @ 512 threads) ----
__device__ __forceinline__ float sigf(float x) { return 1.0f / (1.0f + __expf(-x)); }

__device__ __forceinline__ void grid_bar(int bid, unsigned wantc) {
    __syncthreads();
    if (threadIdx.x < 8) {
        if (threadIdx.x == 0)
            asm volatile("red.release.gpu.global.add.u32 [%0], 1;"
                         :: "l"(&g_bars[(bid & 7) * 32]) : "memory");
        unsigned v;
        do {
            asm volatile("ld.acquire.gpu.global.u32 %0, [%1];"
                         : "=r"(v) : "l"(&g_bars[threadIdx.x * 32]));
        } while (v < wantc);
    }
    __syncthreads();
}

// SMEM byte offsets (R5 layout, red widened to 16 slots)
#define WSTR 1032
#define OFF_WHI 0
#define OFF_WLO (32 * WSTR * 2)                // 66048
#define OFF_HS  (2 * 32 * WSTR * 2)            // 132096
#define HSTR 136
#define HS_HILO (32 * HSTR * 2)                // 8704
#define HS_BUF  (2 * HS_HILO)                  // 17408
#define OFF_RED (OFF_HS + 2 * HS_BUF)          // 166912
#define OFF_GS  (OFF_RED + 16 * 32 * 16 * 4)   // 199680
#define OFF_LEN (OFF_GS + 32 * 36 * 4)         // 204288
#define REC_SMEM (OFF_LEN + 128)               // 204416

__global__ __launch_bounds__(512, 1) void lstm_rec(
    const float* __restrict__ whh, const void* __restrict__ len_raw,
    float* __restrict__ outp, float* __restrict__ cdst, float* __restrict__ hdst)
{
    extern __shared__ char sm[];
    const unsigned sbase = (unsigned)__cvta_generic_to_shared(sm);
    float* red = (float*)(sm + OFF_RED);       // [16 slots][32 m][16 n]
    float* g_s = (float*)(sm + OFF_GS);
    int* len_s = (int*)(sm + OFF_LEN);

    const int tid = threadIdx.x, lane = tid & 31, wid = tid >> 5;
    const int bid = blockIdx.x;
    const int j0 = bid * 8;

    if (tid == 0) {
        const int* L = (const int*)len_raw;
        bool is64 = true;
        for (int i = 1; i < 32; i += 2) if (L[i] != 0) { is64 = false; break; }
        for (int b = 0; b < 32; ++b) len_s[b] = is64 ? L[2 * b] : L[b];
    }

    // stage + split W_hh slice (16 warps: 64 elems per thread)
    {
        const int r = tid & 31;
        const int grow = (r >> 3) * 1024 + j0 + (r & 7);
        const int k0 = (tid >> 5) * 64;
        const float* src = &whh[(size_t)grow * H_ + k0];
        __nv_bfloat162* whi = (__nv_bfloat162*)(sm + OFF_WHI);
        __nv_bfloat162* wlo = (__nv_bfloat162*)(sm + OFF_WLO);
#pragma unroll
        for (int kk = 0; kk < 64; kk += 4) {
            float4 v = *(const float4*)&src[kk];
            __nv_bfloat16 h0 = __float2bfloat16(v.x), h1 = __float2bfloat16(v.y);
            __nv_bfloat16 h2 = __float2bfloat16(v.z), h3 = __float2bfloat16(v.w);
            int e = r * WSTR + k0 + kk;
            whi[e / 2]     = __nv_bfloat162(h0, h1);
            whi[e / 2 + 1] = __nv_bfloat162(h2, h3);
            wlo[e / 2]     = __nv_bfloat162(__float2bfloat16(v.x - __bfloat162float(h0)),
                                            __float2bfloat16(v.y - __bfloat162float(h1)));
            wlo[e / 2 + 1] = __nv_bfloat162(__float2bfloat16(v.z - __bfloat162float(h2)),
                                            __float2bfloat16(v.w - __bfloat162float(h3)));
        }
    }

    // warp roles: kw = k-slice (8), nh = n-half (2)
    const int kw = wid >> 1, nh = wid & 1;
    const unsigned a_off = ((lane & 7) + (lane & 8)) * (WSTR * 2) + ((lane >> 4) * 8) * 2;
    const unsigned b_off = ((nh * 16 + (lane & 7) + (lane >> 4) * 8) * HSTR
                            + ((lane >> 3) & 1) * 8) * 2;

    // h-chunk staging map: 512 threads, 2 uint4 (16 elems) each per chunk
    const int shl = tid >> 8, srem = tid & 255;
    const int sb = srem >> 3, sk = (srem & 7) * 16;        // batch, elem offset
    const unsigned s_dst = OFF_HS + shl * HS_HILO + (sb * HSTR + sk) * 2;

    // reduce / gx map: 512 threads, 2 outputs each (32m x 32n)
    const int rm = tid >> 4, rn2 = (tid & 15) * 2;
    const int rslot_nh = rn2 >> 4, rcol = rn2 & 15;
    const size_t ocol = (size_t)(rm >> 3) * 1024 + j0 + (rm & 7);

    // update map (threads 0..255)
    const int ju = tid & 7, bu = tid >> 3;
    float c_reg = 0.f, h_reg = 0.f;
    if (tid < 256) {
        g_hb[0][0][bu * H_ + j0 + ju] = __float2bfloat16(0.f);
        g_hb[0][1][bu * H_ + j0 + ju] = __float2bfloat16(0.f);
    }

    unsigned wantc = 16;
    grid_bar(bid, wantc);

    for (int t = 0; t < T_; ++t) {
        float gx0 = __ldg(&g_gx[((size_t)rn2 * T_ + t) * G_ + ocol]);
        float gx1 = __ldg(&g_gx[((size_t)(rn2 + 1) * T_ + t) * G_ + ocol]);

        const __nv_bfloat16* hsrc = g_hb[t & 1][shl];
        // prologue: stage chunk 0 (2 uint4 = 16 elems per thread)
        uint4 nxt0 = __ldcg((const uint4*)&hsrc[(size_t)sb * H_ + sk]);
        uint4 nxt1 = __ldcg((const uint4*)&hsrc[(size_t)sb * H_ + sk] + 1);
        *(uint4*)(sm + s_dst)      = nxt0;
        *(uint4*)(sm + s_dst + 16) = nxt1;
        __syncthreads();

        float c[2][2][4];
#pragma unroll
        for (int mi = 0; mi < 2; ++mi)
#pragma unroll
            for (int nj = 0; nj < 2; ++nj)
#pragma unroll
                for (int q = 0; q < 4; ++q) c[mi][nj][q] = 0.f;

        for (int kc = 0; kc < 8; ++kc) {
            if (kc < 7) {
                nxt0 = __ldcg((const uint4*)&hsrc[(size_t)sb * H_ + (kc + 1) * 128 + sk]);
                nxt1 = __ldcg((const uint4*)&hsrc[(size_t)sb * H_ + (kc + 1) * 128 + sk] + 1);
            }
            const unsigned hb_s = sbase + OFF_HS + (kc & 1) * HS_BUF;
            {
                const int kloc = kw * 16;                  // this warp's 16-k slice
                const int kg = kc * 128 + kloc;
                unsigned ah[2][4], al[2][4], bh[4], bl[4];
                unsigned bd = hb_s + b_off + kloc * 2;
                ldsm4(bh, bd);
                ldsm4(bl, bd + HS_HILO);
#pragma unroll
                for (int mi = 0; mi < 2; ++mi) {
                    unsigned ad = sbase + a_off + (mi * 16 * WSTR + kg) * 2;
                    ldsm4(ah[mi], ad + OFF_WHI);
                    ldsm4(al[mi], ad + OFF_WLO);
                }
#pragma unroll
                for (int mi = 0; mi < 2; ++mi)
#pragma unroll
                    for (int nj = 0; nj < 2; ++nj) {
                        mma16816(c[mi][nj], ah[mi], bh[2*nj], bh[2*nj+1]);
                        mma16816(c[mi][nj], ah[mi], bl[2*nj], bl[2*nj+1]);
                        mma16816(c[mi][nj], al[mi], bh[2*nj], bh[2*nj+1]);
                    }
            }
            if (kc < 7) {
                const unsigned nb_s = s_dst + ((kc + 1) & 1) * HS_BUF;
                *(uint4*)(sm + nb_s)      = nxt0;
                *(uint4*)(sm + nb_s + 16) = nxt1;
            }
            __syncthreads();
        }

        // partials: slot = kw*2+nh
#pragma unroll
        for (int mi = 0; mi < 2; ++mi)
#pragma unroll
            for (int nj = 0; nj < 2; ++nj) {
                int m = mi * 16 + (lane >> 2);
                int nl = nj * 8 + (lane & 3) * 2;
                float* rb = &red[((kw * 2 + nh) * 32) * 16];
                *(float2*)&rb[m * 16 + nl]       = make_float2(c[mi][nj][0], c[mi][nj][1]);
                *(float2*)&rb[(m + 8) * 16 + nl] = make_float2(c[mi][nj][2], c[mi][nj][3]);
            }
        __syncthreads();

        // reduce over 8 kw-slots + gx (2 outputs per thread)
        {
            float s0 = gx0, s1 = gx1;
#pragma unroll
            for (int s = 0; s < 8; ++s) {
                float2 p = *(float2*)&red[((s * 2 + rslot_nh) * 32 + rm) * 16 + rcol];
                s0 += p.x; s1 += p.y;
            }
            g_s[rm * 36 + rn2]     = s0;
            g_s[rm * 36 + rn2 + 1] = s1;
        }
        __syncthreads();

        // pointwise update (fp32 state), threads 0..255
        if (tid < 256) {
            float fg = sigf(g_s[(0 * 8 + ju) * 36 + bu]);
            float ig = sigf(g_s[(1 * 8 + ju) * 36 + bu]);
            float og = sigf(g_s[(2 * 8 + ju) * 36 + bu]);
            float cg = tanhf(g_s[(3 * 8 + ju) * 36 + bu]);
            float cn = fg * c_reg + ig * cg;
            float hn = og * tanhf(cn);
            if (t < len_s[bu]) { c_reg = cn; h_reg = hn; }
            __nv_bfloat16 hh = __float2bfloat16(h_reg);
            __nv_bfloat16 hl = __float2bfloat16(h_reg - __bfloat162float(hh));
            int nbuf = (t & 1) ^ 1;
            g_hb[nbuf][0][bu * H_ + j0 + ju] = hh;
            g_hb[nbuf][1][bu * H_ + j0 + ju] = hl;
            outp[((size_t)bu * T_ + t) * H_ + (j0 + ju)] = h_reg;
        }

        wantc += 16;
        grid_bar(bid, wantc);
    }
    if (tid < 256) {
        cdst[(size_t)bu * H_ + j0 + ju] = c_reg;
        hdst[(size_t)bu * H_ + j0 + ju] = h_reg;
    }
}

extern "C" void kernel_launch(void* const* d_in, const int* in_sizes, int n_in,
                              void* d_out, int out_size)
{
    const float* x    = (const float*)d_in[0];
    const void*  len  = d_in[1];
    const float* wih0 = (const float*)d_in[2];
    const float* whh0 = (const float*)d_in[3];
    const float* b0   = (const float*)d_in[4];
    const float* wih1 = (const float*)d_in[5];
    const float* whh1 = (const float*)d_in[6];
    const float* b1   = (const float*)d_in[7];
    float* out = (float*)d_out;

    void *bar_p, *out0_p, *ahi_p, *alo_p, *whi_p, *wlo_p;
    cudaGetSymbolAddress(&bar_p, g_bars);
    cudaGetSymbolAddress(&out0_p, g_out0);
    cudaGetSymbolAddress(&ahi_p, g_Ahi);
    cudaGetSymbolAddress(&alo_p, g_Alo);
    cudaGetSymbolAddress(&whi_p, g_Whi);
    cudaGetSymbolAddress(&wlo_p, g_Wlo);
    float* out0 = (float*)out0_p;
    __nv_bfloat16* Ahi = (__nv_bfloat16*)ahi_p;
    __nv_bfloat16* Alo = (__nv_bfloat16*)alo_p;
    __nv_bfloat16* Whi = (__nv_bfloat16*)whi_p;
    __nv_bfloat16* Wlo = (__nv_bfloat16*)wlo_p;

    cudaFuncSetAttribute(lstm_rec, cudaFuncAttributeMaxDynamicSharedMemorySize, REC_SMEM);
    cudaFuncSetAttribute(tc_gemm, cudaFuncAttributeMaxDynamicSharedMemorySize, TC_SMEM);

    const size_t O1 = (size_t)B_ * T_ * H_;
    float* c0dst = out + O1;
    float* c1dst = out + O1 + (size_t)B_ * H_;
    float* h0dst = out + O1 + 2 * (size_t)B_ * H_;
    float* h1dst = out + O1 + 3 * (size_t)B_ * H_;

    const int nA4 = (B_ * T_ * H_) / 4;
    const int nW4 = (G_ * H_) / 4;
    dim3 gg(G_ / 128, (B_ * T_) / 128);

    conv_split<<<nW4 / 256, 256>>>(wih0, Whi, Wlo, nW4);
    conv_split<<<nA4 / 256, 256>>>(x, Ahi, Alo, nA4);
    tc_gemm<<<gg, 256, TC_SMEM>>>(Ahi, Alo, Whi, Wlo, b0);
    cudaMemsetAsync(bar_p, 0, 8 * 32 * sizeof(unsigned), 0);
    lstm_rec<<<NB, 512, REC_SMEM>>>(whh0, len, out0, c0dst, h0dst);

    conv_split<<<nW4 / 256, 256>>>(wih1, Whi, Wlo, nW4);
    conv_split<<<nA4 / 256, 256>>>(out0, Ahi, Alo, nA4);
    tc_gemm<<<gg, 256, TC_SMEM>>>(Ahi, Alo, Whi, Wlo, b1);
    cudaMemsetAsync(bar_p, 0, 8 * 32 * sizeof(unsigned), 0);
    lstm_rec<<<NB, 512, REC_SMEM>>>(whh1, len, out, c1dst, h1dst);
}